// round 8
// baseline (speedup 1.0000x reference)
#include <cuda_runtime.h>
#include <cuda_bf16.h>
#include <cstdint>

#define HDIM 128
#define MAXN 100000
#define MAXE 1600000

// Scratch (device globals; no allocation allowed).
__device__ float g_agg[(size_t)MAXN * HDIM];
__device__ float g_h0 [(size_t)MAXN * HDIM];
__device__ float g_h1 [(size_t)MAXN * HDIM];
__device__ int   g_offs[MAXN + 1];
__device__ int   g_cursor[MAXN];
__device__ int   g_ssrc[MAXE];

// Fused-layer smem layout (floats): At[128*132], W1s[128*136], W2s[128*136]
#define AT_PITCH 132
#define WT_PITCH 136
#define AT_ELEMS (128 * AT_PITCH)
#define WT_ELEMS (128 * WT_PITCH)
#define FUSED_SMEM_BYTES ((AT_ELEMS + 2 * WT_ELEMS) * 4)

// ---------------------------------------------------------------------------
// Helpers
// ---------------------------------------------------------------------------
__device__ __forceinline__ void atomic_add_f4(float4* addr, float4 v) {
#if __CUDA_ARCH__ >= 900
    atomicAdd(addr, v);
#else
    float* f = (float*)addr;
    atomicAdd(f + 0, v.x); atomicAdd(f + 1, v.y);
    atomicAdd(f + 2, v.z); atomicAdd(f + 3, v.w);
#endif
}

__device__ __forceinline__ uint32_t to_tf32(float x) {
    uint32_t r;
    asm("cvt.rna.tf32.f32 %0, %1;" : "=r"(r) : "f"(x));
    return r;
}

__device__ __forceinline__ void mma_tf32(float d[4],
                                         uint32_t a0, uint32_t a1, uint32_t a2, uint32_t a3,
                                         uint32_t b0, uint32_t b1) {
    asm volatile(
        "mma.sync.aligned.m16n8k8.row.col.f32.tf32.tf32.f32 "
        "{%0,%1,%2,%3}, {%4,%5,%6,%7}, {%8,%9}, {%0,%1,%2,%3};\n"
        : "+f"(d[0]), "+f"(d[1]), "+f"(d[2]), "+f"(d[3])
        : "r"(a0), "r"(a1), "r"(a2), "r"(a3), "r"(b0), "r"(b1));
}

__device__ __forceinline__ uint32_t smem_u32(const void* p) {
    return (uint32_t)__cvta_generic_to_shared(p);
}
__device__ __forceinline__ void cp_async16(uint32_t saddr, const void* gptr) {
    asm volatile("cp.async.cg.shared.global [%0], [%1], 16;\n" :: "r"(saddr), "l"(gptr));
}
__device__ __forceinline__ void cp_commit() {
    asm volatile("cp.async.commit_group;\n");
}
template <int N>
__device__ __forceinline__ void cp_wait() {
    asm volatile("cp.async.wait_group %0;\n" :: "n"(N));
}

// ---------------------------------------------------------------------------
// CSR build kernels
// ---------------------------------------------------------------------------
__global__ void zero_int_kernel(int* __restrict__ p, int n) {
    int i = blockIdx.x * blockDim.x + threadIdx.x;
    if (i < n) p[i] = 0;
}

__global__ void hist_kernel(const int* __restrict__ dst, int* __restrict__ count, int E) {
    int e = blockIdx.x * blockDim.x + threadIdx.x;
    if (e < E) atomicAdd(&count[__ldg(&dst[e])], 1);
}

__global__ __launch_bounds__(1024) void scan_kernel(int* __restrict__ cnt,
                                                    int* __restrict__ offs,
                                                    int N, int C) {
    __shared__ int part[1024];
    const int t = threadIdx.x;
    const int beg = min(t * C, N);
    const int end = min(beg + C, N);
    int s = 0;
    for (int i = beg; i < end; i++) s += cnt[i];
    part[t] = s;
    __syncthreads();
    for (int d = 1; d < 1024; d <<= 1) {
        int val = (t >= d) ? part[t - d] : 0;
        __syncthreads();
        if (t >= d) part[t] += val;
        __syncthreads();
    }
    int run = (t == 0) ? 0 : part[t - 1];
    for (int i = beg; i < end; i++) {
        int c = cnt[i];
        offs[i] = run;
        cnt[i]  = run;
        run += c;
    }
    if (t == 1023) offs[N] = part[1023];
}

__global__ void permute_kernel(const int* __restrict__ src,
                               const int* __restrict__ dst,
                               int* __restrict__ cursor,
                               int* __restrict__ ssrc, int E) {
    int e = blockIdx.x * blockDim.x + threadIdx.x;
    if (e >= E) return;
    int d = __ldg(&dst[e]);
    int pos = atomicAdd(&cursor[d], 1);
    ssrc[pos] = __ldg(&src[e]);
}

// ---------------------------------------------------------------------------
// Gather: agg[n,:] = h[n,:] + sum_{e: dst==n} h[src[e],:]
// ---------------------------------------------------------------------------
__global__ __launch_bounds__(256) void gather_kernel(const float* __restrict__ h,
                                                     const int* __restrict__ ssrc,
                                                     const int* __restrict__ offs,
                                                     float* __restrict__ agg,
                                                     int N) {
    int node = (int)(((size_t)blockIdx.x * blockDim.x + threadIdx.x) >> 5);
    int lane = threadIdx.x & 31;
    if (node >= N) return;
    const float4* hb = (const float4*)h;
    int beg = __ldg(&offs[node]);
    int end = __ldg(&offs[node + 1]);

    float4 v0 = __ldg(hb + (size_t)node * 32 + lane);
    float4 v1 = make_float4(0.f, 0.f, 0.f, 0.f);
    int i = beg;
    for (; i + 1 < end; i += 2) {
        int s0 = __ldg(&ssrc[i]);
        int s1 = __ldg(&ssrc[i + 1]);
        float4 a = __ldg(hb + (size_t)s0 * 32 + lane);
        float4 b = __ldg(hb + (size_t)s1 * 32 + lane);
        v0.x += a.x; v0.y += a.y; v0.z += a.z; v0.w += a.w;
        v1.x += b.x; v1.y += b.y; v1.z += b.z; v1.w += b.w;
    }
    if (i < end) {
        int s0 = __ldg(&ssrc[i]);
        float4 a = __ldg(hb + (size_t)s0 * 32 + lane);
        v0.x += a.x; v0.y += a.y; v0.z += a.z; v0.w += a.w;
    }
    v0.x += v1.x; v0.y += v1.y; v0.z += v1.z; v0.w += v1.w;
    ((float4*)agg)[(size_t)node * 32 + lane] = v0;
}

// ---------------------------------------------------------------------------
// Fused GIN layer MLP: C = relu( relu(A@W1 + b1) @ W2 + b2 )
// Full K=128 resident in smem; z tile reuses the A-tile buffer.
// ---------------------------------------------------------------------------
__device__ __forceinline__ void gemm_full(const float* __restrict__ Ts,
                                          const float* __restrict__ Ws,
                                          float acc[2][8][4],
                                          int warp_m, int warp_n, int g, int c) {
#pragma unroll
    for (int ks = 0; ks < 16; ks++) {
        const int k0 = ks * 8;
        uint32_t a[2][4];
#pragma unroll
        for (int mt = 0; mt < 2; mt++) {
            int rb = warp_m + mt * 16;
            a[mt][0] = to_tf32(Ts[(rb + g    ) * AT_PITCH + k0 + c    ]);
            a[mt][1] = to_tf32(Ts[(rb + 8 + g) * AT_PITCH + k0 + c    ]);
            a[mt][2] = to_tf32(Ts[(rb + g    ) * AT_PITCH + k0 + c + 4]);
            a[mt][3] = to_tf32(Ts[(rb + 8 + g) * AT_PITCH + k0 + c + 4]);
        }
#pragma unroll
        for (int nt = 0; nt < 8; nt++) {
            int n = warp_n + nt * 8 + g;
            uint32_t b0 = to_tf32(Ws[(k0 + c    ) * WT_PITCH + n]);
            uint32_t b1 = to_tf32(Ws[(k0 + 4 + c) * WT_PITCH + n]);
#pragma unroll
            for (int mt = 0; mt < 2; mt++)
                mma_tf32(acc[mt][nt], a[mt][0], a[mt][1], a[mt][2], a[mt][3], b0, b1);
        }
    }
}

__global__ __launch_bounds__(256) void fused_layer_kernel(
    const float* __restrict__ A,
    const float* __restrict__ W1, const float* __restrict__ b1,
    const float* __restrict__ W2, const float* __restrict__ b2,
    float* __restrict__ C,
    int M) {
    extern __shared__ float smem[];
    float* At  = smem;                       // 128 x AT_PITCH (A tile, then z tile)
    float* W1s = smem + AT_ELEMS;            // 128 x WT_PITCH
    float* W2s = W1s + WT_ELEMS;             // 128 x WT_PITCH

    const int tid  = threadIdx.x;
    const int lane = tid & 31;
    const int wid  = tid >> 5;
    const int warp_m = (wid & 3) * 32;
    const int warp_n = (wid >> 2) * 64;
    const int g = lane >> 2;
    const int c = lane & 3;
    const int rowBase = blockIdx.x * 128;

    // --- Load A tile + W1 (group 0), then prefetch W2 (group 1) ---
#pragma unroll
    for (int i = tid; i < 4096; i += 256) {
        int r  = i >> 5;
        int c4 = (i & 31) * 4;
        int gr = rowBase + r;
        float* dst = &At[r * AT_PITCH + c4];
        if (gr < M) cp_async16(smem_u32(dst), &A[(size_t)gr * HDIM + c4]);
        else        *(float4*)dst = make_float4(0.f, 0.f, 0.f, 0.f);
    }
#pragma unroll
    for (int i = tid; i < 4096; i += 256) {
        int r  = i >> 5;
        int c4 = (i & 31) * 4;
        cp_async16(smem_u32(&W1s[r * WT_PITCH + c4]), &W1[(size_t)r * HDIM + c4]);
    }
    cp_commit();
#pragma unroll
    for (int i = tid; i < 4096; i += 256) {
        int r  = i >> 5;
        int c4 = (i & 31) * 4;
        cp_async16(smem_u32(&W2s[r * WT_PITCH + c4]), &W2[(size_t)r * HDIM + c4]);
    }
    cp_commit();
    cp_wait<1>();           // A + W1 resident; W2 still in flight
    __syncthreads();

    float acc[2][8][4];
#pragma unroll
    for (int mt = 0; mt < 2; mt++)
#pragma unroll
        for (int nt = 0; nt < 8; nt++)
#pragma unroll
            for (int j = 0; j < 4; j++) acc[mt][nt][j] = 0.f;

    // --- GEMM1: z = relu(A @ W1 + b1) ---
    gemm_full(At, W1s, acc, warp_m, warp_n, g, c);
    __syncthreads();        // all reads of At complete before overwrite

    // Write z into At (raw fp32; cvt at fragment build, same numerics as before)
#pragma unroll
    for (int nt = 0; nt < 8; nt++) {
        int col = warp_n + nt * 8 + 2 * c;
        float2 bb = *(const float2*)&b1[col];
#pragma unroll
        for (int mt = 0; mt < 2; mt++) {
            int r0 = warp_m + mt * 16 + g;
            int r1 = r0 + 8;
            float2 z0, z1;
            z0.x = fmaxf(acc[mt][nt][0] + bb.x, 0.f);
            z0.y = fmaxf(acc[mt][nt][1] + bb.y, 0.f);
            z1.x = fmaxf(acc[mt][nt][2] + bb.x, 0.f);
            z1.y = fmaxf(acc[mt][nt][3] + bb.y, 0.f);
            *(float2*)&At[r0 * AT_PITCH + col] = z0;
            *(float2*)&At[r1 * AT_PITCH + col] = z1;
        }
    }
    cp_wait<0>();           // W2 resident
    __syncthreads();        // z visible to all warps

#pragma unroll
    for (int mt = 0; mt < 2; mt++)
#pragma unroll
        for (int nt = 0; nt < 8; nt++)
#pragma unroll
            for (int j = 0; j < 4; j++) acc[mt][nt][j] = 0.f;

    // --- GEMM2: h = relu(z @ W2 + b2) ---
    gemm_full(At, W2s, acc, warp_m, warp_n, g, c);

    // Epilogue to gmem
#pragma unroll
    for (int nt = 0; nt < 8; nt++) {
        int col = warp_n + nt * 8 + 2 * c;
        float2 bb = *(const float2*)&b2[col];
#pragma unroll
        for (int mt = 0; mt < 2; mt++) {
            int row0 = rowBase + warp_m + mt * 16 + g;
            int row1 = row0 + 8;
            if (row0 < M) {
                float2 o;
                o.x = fmaxf(acc[mt][nt][0] + bb.x, 0.f);
                o.y = fmaxf(acc[mt][nt][1] + bb.y, 0.f);
                *(float2*)&C[(size_t)row0 * HDIM + col] = o;
            }
            if (row1 < M) {
                float2 o;
                o.x = fmaxf(acc[mt][nt][2] + bb.x, 0.f);
                o.y = fmaxf(acc[mt][nt][3] + bb.y, 0.f);
                *(float2*)&C[(size_t)row1 * HDIM + col] = o;
            }
        }
    }
}

// ---------------------------------------------------------------------------
// Final zero + pool
// ---------------------------------------------------------------------------
__global__ void zero_kernel(float4* __restrict__ p, size_t n4) {
    size_t i = (size_t)blockIdx.x * blockDim.x + threadIdx.x;
    if (i < n4) p[i] = make_float4(0.f, 0.f, 0.f, 0.f);
}

__global__ void pool_kernel(const float* __restrict__ h,
                            const int* __restrict__ batch,
                            float* __restrict__ out,
                            int M) {
    int warp = (int)(((size_t)blockIdx.x * blockDim.x + threadIdx.x) >> 5);
    int lane = threadIdx.x & 31;
    if (warp >= M) return;
    int g = __ldg(&batch[warp]);
    float4 v = __ldg(((const float4*)(h + (size_t)warp * HDIM)) + lane);
    atomic_add_f4(((float4*)(out + (size_t)g * HDIM)) + lane, v);
}

// ---------------------------------------------------------------------------
// Launch
// ---------------------------------------------------------------------------
extern "C" void kernel_launch(void* const* d_in, const int* in_sizes, int n_in,
                              void* d_out, int out_size) {
    const float* x     = (const float*)d_in[0];
    const int*   ei    = (const int*)d_in[1];
    const int*   batch = (const int*)d_in[2];
    const float* W1[3] = {(const float*)d_in[3], (const float*)d_in[7],  (const float*)d_in[11]};
    const float* b1[3] = {(const float*)d_in[4], (const float*)d_in[8],  (const float*)d_in[12]};
    const float* W2[3] = {(const float*)d_in[5], (const float*)d_in[9],  (const float*)d_in[13]};
    const float* b2[3] = {(const float*)d_in[6], (const float*)d_in[10], (const float*)d_in[14]};

    const int Nn = in_sizes[0] / HDIM;
    const int Ee = in_sizes[1] / 2;
    const int* src = ei;
    const int* dst = ei + Ee;

    float *agg, *h0, *h1;
    int *offs, *cursor, *ssrc;
    cudaGetSymbolAddress((void**)&agg,    g_agg);
    cudaGetSymbolAddress((void**)&h0,     g_h0);
    cudaGetSymbolAddress((void**)&h1,     g_h1);
    cudaGetSymbolAddress((void**)&offs,   g_offs);
    cudaGetSymbolAddress((void**)&cursor, g_cursor);
    cudaGetSymbolAddress((void**)&ssrc,   g_ssrc);
    float* hbuf[2] = {h0, h1};

    cudaFuncSetAttribute(fused_layer_kernel,
                         cudaFuncAttributeMaxDynamicSharedMemorySize, FUSED_SMEM_BYTES);

    // --- Build CSR (dst-sorted src list), once per call ---
    zero_int_kernel<<<(Nn + 255) / 256, 256>>>(cursor, Nn);
    hist_kernel<<<(Ee + 255) / 256, 256>>>(dst, cursor, Ee);
    const int C = (Nn + 1023) / 1024;
    scan_kernel<<<1, 1024>>>(cursor, offs, Nn, C);
    permute_kernel<<<(Ee + 255) / 256, 256>>>(src, dst, cursor, ssrc, Ee);

    const int gm_blocks   = (Nn + 127) / 128;
    const int ga_blocks   = (Nn + 7) / 8;
    const int pool_blocks = (Nn + 7) / 8;

    const float* hin = x;
    for (int layer = 0; layer < 3; layer++) {
        float* hout = hbuf[layer & 1];
        gather_kernel<<<ga_blocks, 256>>>(hin, ssrc, offs, agg, Nn);
        fused_layer_kernel<<<gm_blocks, 256, FUSED_SMEM_BYTES>>>(
            agg, W1[layer], b1[layer], W2[layer], b2[layer], hout, Nn);
        hin = hout;
    }

    float* out = (float*)d_out;
    const int zo_blocks = (out_size / 4 + 255) / 256;
    zero_kernel<<<zo_blocks, 256>>>((float4*)out, out_size / 4);
    pool_kernel<<<pool_blocks, 256>>>(hin, batch, out, Nn);
}

// round 9
// speedup vs baseline: 1.3193x; 1.3193x over previous
#include <cuda_runtime.h>
#include <cuda_bf16.h>
#include <cstdint>

#define HDIM 128
#define MAXN 100000
#define MAXE 1600000
#define NB_MAX 128          // max scan blocks: ceil(100000/1024) = 98

// Scratch (device globals; no allocation allowed).
__device__ float g_agg[(size_t)MAXN * HDIM];
__device__ float g_z  [(size_t)MAXN * HDIM];
__device__ float g_h0 [(size_t)MAXN * HDIM];
__device__ float g_h1 [(size_t)MAXN * HDIM];
__device__ int   g_offs[MAXN + 1];
__device__ int   g_cursor[MAXN];
__device__ int   g_ssrc[MAXE];
__device__ int   g_bsum[NB_MAX + 1];
__device__ float g_wt[6][HDIM * HDIM];   // pre-rounded tf32 weights

// GEMM dynamic smem (floats): As0[128*36] Ws0[32*136] As1 Ws1
#define AS_PITCH 36
#define WS_PITCH 136
#define AS_ELEMS (128 * AS_PITCH)
#define WS_ELEMS (32 * WS_PITCH)
#define GEMM_SMEM_BYTES ((AS_ELEMS + WS_ELEMS) * 2 * 4)

// ---------------------------------------------------------------------------
// Helpers
// ---------------------------------------------------------------------------
__device__ __forceinline__ void atomic_add_f4(float4* addr, float4 v) {
#if __CUDA_ARCH__ >= 900
    atomicAdd(addr, v);
#else
    float* f = (float*)addr;
    atomicAdd(f + 0, v.x); atomicAdd(f + 1, v.y);
    atomicAdd(f + 2, v.z); atomicAdd(f + 3, v.w);
#endif
}

__device__ __forceinline__ uint32_t to_tf32(float x) {
    uint32_t r;
    asm("cvt.rna.tf32.f32 %0, %1;" : "=r"(r) : "f"(x));
    return r;
}
__device__ __forceinline__ float round_tf32(float x) {
    return __uint_as_float(to_tf32(x));
}

__device__ __forceinline__ void mma_tf32(float d[4],
                                         uint32_t a0, uint32_t a1, uint32_t a2, uint32_t a3,
                                         uint32_t b0, uint32_t b1) {
    asm volatile(
        "mma.sync.aligned.m16n8k8.row.col.f32.tf32.tf32.f32 "
        "{%0,%1,%2,%3}, {%4,%5,%6,%7}, {%8,%9}, {%0,%1,%2,%3};\n"
        : "+f"(d[0]), "+f"(d[1]), "+f"(d[2]), "+f"(d[3])
        : "r"(a0), "r"(a1), "r"(a2), "r"(a3), "r"(b0), "r"(b1));
}

__device__ __forceinline__ uint32_t smem_u32(const void* p) {
    return (uint32_t)__cvta_generic_to_shared(p);
}
__device__ __forceinline__ void cp_async16(uint32_t saddr, const void* gptr) {
    asm volatile("cp.async.cg.shared.global [%0], [%1], 16;\n" :: "r"(saddr), "l"(gptr));
}
__device__ __forceinline__ void cp_commit() {
    asm volatile("cp.async.commit_group;\n");
}
template <int N>
__device__ __forceinline__ void cp_wait() {
    asm volatile("cp.async.wait_group %0;\n" :: "n"(N));
}

// ---------------------------------------------------------------------------
// Weight pre-round: dst[i] = tf32_round(src[i])
// ---------------------------------------------------------------------------
__global__ void round_w_kernel(float* __restrict__ dst, const float* __restrict__ src, int n) {
    int i = blockIdx.x * blockDim.x + threadIdx.x;
    if (i < n) dst[i] = round_tf32(src[i]);
}

// ---------------------------------------------------------------------------
// CSR build
// ---------------------------------------------------------------------------
__global__ void zero_int_kernel(int* __restrict__ p, int n) {
    int i = blockIdx.x * blockDim.x + threadIdx.x;
    if (i < n) p[i] = 0;
}

__global__ void hist_kernel(const int* __restrict__ dst, int* __restrict__ count, int E) {
    int e = blockIdx.x * blockDim.x + threadIdx.x;
    if (e < E) atomicAdd(&count[__ldg(&dst[e])], 1);
}

// scan1: per-block exclusive scan of 1024 counts -> offs; block total -> bsum
__global__ __launch_bounds__(1024) void scan1_kernel(const int* __restrict__ cnt,
                                                     int* __restrict__ offs,
                                                     int* __restrict__ bsum, int N) {
    __shared__ int sh[1024];
    int t = threadIdx.x;
    int i = blockIdx.x * 1024 + t;
    int v = (i < N) ? cnt[i] : 0;
    sh[t] = v;
    __syncthreads();
    for (int d = 1; d < 1024; d <<= 1) {
        int x = (t >= d) ? sh[t - d] : 0;
        __syncthreads();
        if (t >= d) sh[t] += x;
        __syncthreads();
    }
    if (i < N) offs[i] = sh[t] - v;            // exclusive within block
    if (t == 1023) bsum[blockIdx.x] = sh[1023]; // block total
}

// scan2: single block exclusive-scans nb block sums; bsum[nb] = grand total
__global__ __launch_bounds__(NB_MAX) void scan2_kernel(int* __restrict__ bsum, int nb) {
    __shared__ int sh[NB_MAX];
    int t = threadIdx.x;
    int v = (t < nb) ? bsum[t] : 0;
    sh[t] = v;
    __syncthreads();
    for (int d = 1; d < NB_MAX; d <<= 1) {
        int x = (t >= d) ? sh[t - d] : 0;
        __syncthreads();
        if (t >= d) sh[t] += x;
        __syncthreads();
    }
    if (t < nb) bsum[t] = sh[t] - v;            // exclusive
    if (t == 0) bsum[nb] = sh[nb - 1];          // total
}

// scan3: add block offsets; copy into cursor; write offs[N]
__global__ __launch_bounds__(1024) void scan3_kernel(int* __restrict__ offs,
                                                     int* __restrict__ cursor,
                                                     const int* __restrict__ bsum,
                                                     int N, int nb) {
    int i = blockIdx.x * 1024 + threadIdx.x;
    if (i < N) {
        int v = offs[i] + bsum[blockIdx.x];
        offs[i] = v;
        cursor[i] = v;
    }
    if (i == 0) offs[N] = bsum[nb];
}

__global__ void permute_kernel(const int* __restrict__ src,
                               const int* __restrict__ dst,
                               int* __restrict__ cursor,
                               int* __restrict__ ssrc, int E) {
    int e = blockIdx.x * blockDim.x + threadIdx.x;
    if (e >= E) return;
    int d = __ldg(&dst[e]);
    int pos = atomicAdd(&cursor[d], 1);
    ssrc[pos] = __ldg(&src[e]);
}

// ---------------------------------------------------------------------------
// Gather: agg[n,:] = tf32_round( h[n,:] + sum_{e: dst==n} h[src[e],:] )
// (rounding here = what GEMM's cvt would do; cvt is idempotent -> bit-identical)
// ---------------------------------------------------------------------------
__global__ __launch_bounds__(256) void gather_kernel(const float* __restrict__ h,
                                                     const int* __restrict__ ssrc,
                                                     const int* __restrict__ offs,
                                                     float* __restrict__ agg,
                                                     int N) {
    int node = (int)(((size_t)blockIdx.x * blockDim.x + threadIdx.x) >> 5);
    int lane = threadIdx.x & 31;
    if (node >= N) return;
    const float4* hb = (const float4*)h;
    int beg = __ldg(&offs[node]);
    int end = __ldg(&offs[node + 1]);

    float4 v0 = __ldg(hb + (size_t)node * 32 + lane);
    float4 v1 = make_float4(0.f, 0.f, 0.f, 0.f);
    int i = beg;
    for (; i + 1 < end; i += 2) {
        int s0 = __ldg(&ssrc[i]);
        int s1 = __ldg(&ssrc[i + 1]);
        float4 a = __ldg(hb + (size_t)s0 * 32 + lane);
        float4 b = __ldg(hb + (size_t)s1 * 32 + lane);
        v0.x += a.x; v0.y += a.y; v0.z += a.z; v0.w += a.w;
        v1.x += b.x; v1.y += b.y; v1.z += b.z; v1.w += b.w;
    }
    if (i < end) {
        int s0 = __ldg(&ssrc[i]);
        float4 a = __ldg(hb + (size_t)s0 * 32 + lane);
        v0.x += a.x; v0.y += a.y; v0.z += a.z; v0.w += a.w;
    }
    v0.x = round_tf32(v0.x + v1.x);
    v0.y = round_tf32(v0.y + v1.y);
    v0.z = round_tf32(v0.z + v1.z);
    v0.w = round_tf32(v0.w + v1.w);
    ((float4*)agg)[(size_t)node * 32 + lane] = v0;
}

// ---------------------------------------------------------------------------
// Tensor-core GEMM, cp.async double-buffered; inputs pre-rounded to tf32 so
// the inner loop has ZERO cvt. ROUND_OUT rounds the stored output (for z).
// ---------------------------------------------------------------------------
__device__ __forceinline__ void gemm_load_stage(
    const float* __restrict__ A, const float* __restrict__ W,
    float* As, float* Ws, int rowBase, int kc, int M, int tid) {
#pragma unroll
    for (int i = tid; i < 1024; i += 256) {
        int r  = i >> 3;
        int c4 = (i & 7) * 4;
        int gr = rowBase + r;
        float* dst = &As[r * AS_PITCH + c4];
        if (gr < M) {
            cp_async16(smem_u32(dst), &A[(size_t)gr * HDIM + kc + c4]);
        } else {
            *(float4*)dst = make_float4(0.f, 0.f, 0.f, 0.f);
        }
    }
#pragma unroll
    for (int i = tid; i < 1024; i += 256) {
        int r  = i >> 5;
        int c4 = (i & 31) * 4;
        cp_async16(smem_u32(&Ws[r * WS_PITCH + c4]), &W[(size_t)(kc + r) * HDIM + c4]);
    }
}

template <bool ROUND_OUT>
__global__ __launch_bounds__(256) void gemm_tc_kernel(
    const float* __restrict__ A,
    const float* __restrict__ W,      // pre-rounded tf32 values
    const float* __restrict__ bias,
    float* __restrict__ C,
    int M) {
    extern __shared__ float smem[];
    float* Asb[2] = {smem, smem + AS_ELEMS + WS_ELEMS};
    float* Wsb[2] = {smem + AS_ELEMS, smem + 2 * AS_ELEMS + WS_ELEMS};

    const int tid  = threadIdx.x;
    const int lane = tid & 31;
    const int wid  = tid >> 5;
    const int warp_m = (wid & 3) * 32;
    const int warp_n = (wid >> 2) * 64;
    const int g = lane >> 2;
    const int c = lane & 3;
    const int rowBase = blockIdx.x * 128;

    float acc[2][8][4];
#pragma unroll
    for (int mt = 0; mt < 2; mt++)
#pragma unroll
        for (int nt = 0; nt < 8; nt++)
#pragma unroll
            for (int j = 0; j < 4; j++) acc[mt][nt][j] = 0.f;

    gemm_load_stage(A, W, Asb[0], Wsb[0], rowBase, 0, M, tid);
    cp_commit();

#pragma unroll
    for (int ci = 0; ci < 4; ci++) {
        if (ci < 3) {
            gemm_load_stage(A, W, Asb[(ci + 1) & 1], Wsb[(ci + 1) & 1],
                            rowBase, (ci + 1) * 32, M, tid);
            cp_commit();
            cp_wait<1>();
        } else {
            cp_wait<0>();
        }
        __syncthreads();

        const uint32_t* As = (const uint32_t*)Asb[ci & 1];
        const uint32_t* Ws = (const uint32_t*)Wsb[ci & 1];
#pragma unroll
        for (int ks = 0; ks < 4; ks++) {
            const int k0 = ks * 8;
            uint32_t a[2][4];
#pragma unroll
            for (int mt = 0; mt < 2; mt++) {
                int rb = warp_m + mt * 16;
                a[mt][0] = As[(rb + g    ) * AS_PITCH + k0 + c    ];
                a[mt][1] = As[(rb + 8 + g) * AS_PITCH + k0 + c    ];
                a[mt][2] = As[(rb + g    ) * AS_PITCH + k0 + c + 4];
                a[mt][3] = As[(rb + 8 + g) * AS_PITCH + k0 + c + 4];
            }
#pragma unroll
            for (int nt = 0; nt < 8; nt++) {
                int n = warp_n + nt * 8 + g;
                uint32_t b0 = Ws[(k0 + c    ) * WS_PITCH + n];
                uint32_t b1 = Ws[(k0 + 4 + c) * WS_PITCH + n];
#pragma unroll
                for (int mt = 0; mt < 2; mt++)
                    mma_tf32(acc[mt][nt], a[mt][0], a[mt][1], a[mt][2], a[mt][3], b0, b1);
            }
        }
        __syncthreads();
    }

#pragma unroll
    for (int nt = 0; nt < 8; nt++) {
        int col = warp_n + nt * 8 + 2 * c;
        float2 bb = *(const float2*)&bias[col];
#pragma unroll
        for (int mt = 0; mt < 2; mt++) {
            int row0 = rowBase + warp_m + mt * 16 + g;
            int row1 = row0 + 8;
            if (row0 < M) {
                float2 o;
                o.x = fmaxf(acc[mt][nt][0] + bb.x, 0.f);
                o.y = fmaxf(acc[mt][nt][1] + bb.y, 0.f);
                if (ROUND_OUT) { o.x = round_tf32(o.x); o.y = round_tf32(o.y); }
                *(float2*)&C[(size_t)row0 * HDIM + col] = o;
            }
            if (row1 < M) {
                float2 o;
                o.x = fmaxf(acc[mt][nt][2] + bb.x, 0.f);
                o.y = fmaxf(acc[mt][nt][3] + bb.y, 0.f);
                if (ROUND_OUT) { o.x = round_tf32(o.x); o.y = round_tf32(o.y); }
                *(float2*)&C[(size_t)row1 * HDIM + col] = o;
            }
        }
    }
}

// ---------------------------------------------------------------------------
// Final zero + pool
// ---------------------------------------------------------------------------
__global__ void zero_kernel(float4* __restrict__ p, size_t n4) {
    size_t i = (size_t)blockIdx.x * blockDim.x + threadIdx.x;
    if (i < n4) p[i] = make_float4(0.f, 0.f, 0.f, 0.f);
}

__global__ void pool_kernel(const float* __restrict__ h,
                            const int* __restrict__ batch,
                            float* __restrict__ out,
                            int M) {
    int warp = (int)(((size_t)blockIdx.x * blockDim.x + threadIdx.x) >> 5);
    int lane = threadIdx.x & 31;
    if (warp >= M) return;
    int g = __ldg(&batch[warp]);
    float4 v = __ldg(((const float4*)(h + (size_t)warp * HDIM)) + lane);
    atomic_add_f4(((float4*)(out + (size_t)g * HDIM)) + lane, v);
}

// ---------------------------------------------------------------------------
// Launch
// ---------------------------------------------------------------------------
extern "C" void kernel_launch(void* const* d_in, const int* in_sizes, int n_in,
                              void* d_out, int out_size) {
    const float* x     = (const float*)d_in[0];
    const int*   ei    = (const int*)d_in[1];
    const int*   batch = (const int*)d_in[2];
    const float* Wsrc[6] = {(const float*)d_in[3], (const float*)d_in[5],
                            (const float*)d_in[7], (const float*)d_in[9],
                            (const float*)d_in[11], (const float*)d_in[13]};
    const float* b1[3] = {(const float*)d_in[4], (const float*)d_in[8],  (const float*)d_in[12]};
    const float* b2[3] = {(const float*)d_in[6], (const float*)d_in[10], (const float*)d_in[14]};

    const int Nn = in_sizes[0] / HDIM;
    const int Ee = in_sizes[1] / 2;
    const int* src = ei;
    const int* dst = ei + Ee;

    float *agg, *zbuf, *h0, *h1, *wt;
    int *offs, *cursor, *ssrc, *bsum;
    cudaGetSymbolAddress((void**)&agg,    g_agg);
    cudaGetSymbolAddress((void**)&zbuf,   g_z);
    cudaGetSymbolAddress((void**)&h0,     g_h0);
    cudaGetSymbolAddress((void**)&h1,     g_h1);
    cudaGetSymbolAddress((void**)&offs,   g_offs);
    cudaGetSymbolAddress((void**)&cursor, g_cursor);
    cudaGetSymbolAddress((void**)&ssrc,   g_ssrc);
    cudaGetSymbolAddress((void**)&bsum,   g_bsum);
    cudaGetSymbolAddress((void**)&wt,     g_wt);
    float* hbuf[2] = {h0, h1};

    cudaFuncSetAttribute(gemm_tc_kernel<true>,
                         cudaFuncAttributeMaxDynamicSharedMemorySize, GEMM_SMEM_BYTES);
    cudaFuncSetAttribute(gemm_tc_kernel<false>,
                         cudaFuncAttributeMaxDynamicSharedMemorySize, GEMM_SMEM_BYTES);

    // --- Pre-round weights to tf32 (bit-identical to in-GEMM cvt) ---
    for (int i = 0; i < 6; i++)
        round_w_kernel<<<(HDIM * HDIM + 255) / 256, 256>>>(wt + (size_t)i * HDIM * HDIM,
                                                           Wsrc[i], HDIM * HDIM);

    // --- Build CSR (dst-sorted src list) ---
    const int nb = (Nn + 1023) / 1024;
    zero_int_kernel<<<(Nn + 255) / 256, 256>>>(cursor, Nn);
    hist_kernel<<<(Ee + 255) / 256, 256>>>(dst, cursor, Ee);
    scan1_kernel<<<nb, 1024>>>(cursor, offs, bsum, Nn);
    scan2_kernel<<<1, NB_MAX>>>(bsum, nb);
    scan3_kernel<<<nb, 1024>>>(offs, cursor, bsum, Nn, nb);
    permute_kernel<<<(Ee + 255) / 256, 256>>>(src, dst, cursor, ssrc, Ee);

    const int gm_blocks   = (Nn + 127) / 128;
    const int ga_blocks   = (Nn + 7) / 8;
    const int pool_blocks = (Nn + 7) / 8;

    const float* hin = x;
    for (int layer = 0; layer < 3; layer++) {
        float* hout = hbuf[layer & 1];
        const float* w1 = wt + (size_t)(2 * layer)     * HDIM * HDIM;
        const float* w2 = wt + (size_t)(2 * layer + 1) * HDIM * HDIM;
        gather_kernel<<<ga_blocks, 256>>>(hin, ssrc, offs, agg, Nn);
        gemm_tc_kernel<true ><<<gm_blocks, 256, GEMM_SMEM_BYTES>>>(agg,  w1, b1[layer], zbuf, Nn);
        gemm_tc_kernel<false><<<gm_blocks, 256, GEMM_SMEM_BYTES>>>(zbuf, w2, b2[layer], hout, Nn);
        hin = hout;
    }

    float* out = (float*)d_out;
    const int zo_blocks = (out_size / 4 + 255) / 256;
    zero_kernel<<<zo_blocks, 256>>>((float4*)out, out_size / 4);
    pool_kernel<<<pool_blocks, 256>>>(hin, batch, out, Nn);
}